// round 13
// baseline (speedup 1.0000x reference)
#include <cuda_runtime.h>
#include <cstdint>

// Problem constants
#define BATCH 8
#define NNODE 2048
#define DIN   256
#define DOUT  128
#define ALPHA 0.2f

// Scratch (device globals: allocation-free)
__device__ float g_wh[BATCH * NNODE * DOUT];   // 8 MB
__device__ float g_s[BATCH * NNODE];
__device__ float g_d[BATCH * NNODE];

// ---------------------------------------------------------------------------
// Kernel A: wh[r][o] = sum_k x[r][k] * W[o][k],  r in [0, 16384), o in [0,128)
// CTA: 128 rows x 128 cols, 256 threads, 8x8 micro-tile, BK=16
// ---------------------------------------------------------------------------
__global__ __launch_bounds__(256) void wh_kernel(const float* __restrict__ x,
                                                 const float* __restrict__ W) {
    __shared__ float xs[16][132];   // xs[k][row]   (transposed, padded to mult of 4)
    __shared__ float ws[16][132];   // ws[k][o]

    const int tid = threadIdx.x;
    const int ty = tid >> 4;        // 0..15
    const int tx = tid & 15;        // 0..15
    const int row0 = blockIdx.x * 128;

    float acc[8][8];
#pragma unroll
    for (int m = 0; m < 8; m++)
#pragma unroll
        for (int n = 0; n < 8; n++) acc[m][n] = 0.f;

    for (int k0 = 0; k0 < DIN; k0 += 16) {
        // load x tile (128 rows x 16 k) transposed into xs
#pragma unroll
        for (int t = 0; t < 2; t++) {
            int lin4 = t * 256 + tid;          // 0..511 float4s
            int r  = lin4 >> 2;                // 0..127
            int c4 = lin4 & 3;                 // 0..3
            float4 v = *(const float4*)(x + (size_t)(row0 + r) * DIN + k0 + c4 * 4);
            xs[c4 * 4 + 0][r] = v.x;
            xs[c4 * 4 + 1][r] = v.y;
            xs[c4 * 4 + 2][r] = v.z;
            xs[c4 * 4 + 3][r] = v.w;
        }
        // load W tile (128 o x 16 k) transposed into ws
#pragma unroll
        for (int t = 0; t < 2; t++) {
            int lin4 = t * 256 + tid;
            int o  = lin4 >> 2;
            int c4 = lin4 & 3;
            float4 v = *(const float4*)(W + (size_t)o * DIN + k0 + c4 * 4);
            ws[c4 * 4 + 0][o] = v.x;
            ws[c4 * 4 + 1][o] = v.y;
            ws[c4 * 4 + 2][o] = v.z;
            ws[c4 * 4 + 3][o] = v.w;
        }
        __syncthreads();

#pragma unroll
        for (int k = 0; k < 16; k++) {
            float a[8], b[8];
            *(float4*)(a)     = *(const float4*)&xs[k][ty * 8];
            *(float4*)(a + 4) = *(const float4*)&xs[k][ty * 8 + 4];
            *(float4*)(b)     = *(const float4*)&ws[k][tx * 8];
            *(float4*)(b + 4) = *(const float4*)&ws[k][tx * 8 + 4];
#pragma unroll
            for (int m = 0; m < 8; m++)
#pragma unroll
                for (int n = 0; n < 8; n++) acc[m][n] += a[m] * b[n];
        }
        __syncthreads();
    }

#pragma unroll
    for (int m = 0; m < 8; m++) {
        int r = row0 + ty * 8 + m;
        float4 v0 = make_float4(acc[m][0], acc[m][1], acc[m][2], acc[m][3]);
        float4 v1 = make_float4(acc[m][4], acc[m][5], acc[m][6], acc[m][7]);
        *(float4*)(g_wh + (size_t)r * DOUT + tx * 8)     = v0;
        *(float4*)(g_wh + (size_t)r * DOUT + tx * 8 + 4) = v1;
    }
}

// ---------------------------------------------------------------------------
// Kernel S: s[r] = wh[r] . a_src,  d[r] = wh[r] . a_dst.  One warp per row.
// ---------------------------------------------------------------------------
__global__ __launch_bounds__(256) void sd_kernel(const float* __restrict__ a) {
    int row  = blockIdx.x * 8 + (threadIdx.x >> 5);
    int lane = threadIdx.x & 31;
    const float* whr = g_wh + (size_t)row * DOUT;
    float s = 0.f, d = 0.f;
#pragma unroll
    for (int t = 0; t < 4; t++) {
        int o = lane + t * 32;
        float v = whr[o];
        s += v * a[o];
        d += v * a[DOUT + o];
    }
#pragma unroll
    for (int off = 16; off > 0; off >>= 1) {
        s += __shfl_xor_sync(0xFFFFFFFFu, s, off);
        d += __shfl_xor_sync(0xFFFFFFFFu, d, off);
    }
    if (lane == 0) {
        g_s[row] = s;
        g_d[row] = d;
    }
}

// ---------------------------------------------------------------------------
// Kernel B: fused attention.
//   For each (b, row-tile of 128): loop over 16 column tiles of 128,
//   build w[i][j] = adj ? exp(lrelu(s_i + d_j)) : 0 in SMEM (stored transposed),
//   accumulate out[i][o] += w @ wh_tile and denom[i] += rowsum(w).
//   Epilogue: out = relu(out / denom).
// ---------------------------------------------------------------------------
#define WTS_STRIDE 132
#define SMEM_B_BYTES ((128*128 + 128*WTS_STRIDE + 128 + 128) * 4)

__global__ __launch_bounds__(256) void attn_kernel(const int* __restrict__ adj,
                                                   float* __restrict__ out) {
    extern __shared__ float sm[];
    float* whs   = sm;                           // [128][128]  wh tile (j-major)
    float* wts   = whs + 128 * 128;              // [128][132]  w transposed: wts[j][i]
    float* s_s   = wts + 128 * WTS_STRIDE;       // [128]
    float* denom = s_s + 128;                    // [128]

    const int tid = threadIdx.x;
    const int ty = tid >> 4;
    const int tx = tid & 15;
    const int b  = blockIdx.y;          // 0..7
    const int i0 = blockIdx.x * 128;    // row tile base

    if (tid < 128) {
        s_s[tid]   = g_s[b * NNODE + i0 + tid];
        denom[tid] = 0.f;
    }

    float acc[8][8];
#pragma unroll
    for (int m = 0; m < 8; m++)
#pragma unroll
        for (int n = 0; n < 8; n++) acc[m][n] = 0.f;

    __syncthreads();

    for (int jt = 0; jt < 16; jt++) {
        const int j0 = jt * 128;

        // --- load wh tile: whs[j][o] (coalesced float4) ---
#pragma unroll
        for (int t = 0; t < 16; t++) {
            int lin4 = t * 256 + tid;        // 0..4095 float4s
            int j  = lin4 >> 5;              // 32 float4 per row
            int o4 = lin4 & 31;
            *(float4*)(whs + j * 128 + o4 * 4) =
                *(const float4*)(g_wh + ((size_t)(b * NNODE + j0 + j)) * DOUT + o4 * 4);
        }

        // --- build w tile (transposed): wts[jl][il] ---
#pragma unroll 4
        for (int t = 0; t < 64; t++) {
            int lin = t * 256 + tid;
            int jl = lin & 127;
            int il = lin >> 7;
            int av = adj[((size_t)(b * NNODE + i0 + il)) * NNODE + j0 + jl];
            float e  = s_s[il] + g_d[b * NNODE + j0 + jl];
            float lr = fmaxf(e, ALPHA * e);
            float w  = (av != 0) ? __expf(lr) : 0.f;
            wts[jl * WTS_STRIDE + il] = w;
        }
        __syncthreads();

        // --- GEMM: acc[i][o] += sum_j w[i][j] * wh[j][o] ---
#pragma unroll 4
        for (int k = 0; k < 128; k++) {
            float a[8], bb[8];
            *(float4*)(a)      = *(const float4*)(wts + k * WTS_STRIDE + ty * 8);
            *(float4*)(a + 4)  = *(const float4*)(wts + k * WTS_STRIDE + ty * 8 + 4);
            *(float4*)(bb)     = *(const float4*)(whs + k * 128 + tx * 8);
            *(float4*)(bb + 4) = *(const float4*)(whs + k * 128 + tx * 8 + 4);
#pragma unroll
            for (int m = 0; m < 8; m++)
#pragma unroll
                for (int n = 0; n < 8; n++) acc[m][n] += a[m] * bb[n];
        }

        // --- denom accumulation (threads 0..127, one row each) ---
        if (tid < 128) {
            float s0 = 0.f, s1 = 0.f, s2 = 0.f, s3 = 0.f;
#pragma unroll 4
            for (int j = 0; j < 128; j += 4) {
                s0 += wts[(j + 0) * WTS_STRIDE + tid];
                s1 += wts[(j + 1) * WTS_STRIDE + tid];
                s2 += wts[(j + 2) * WTS_STRIDE + tid];
                s3 += wts[(j + 3) * WTS_STRIDE + tid];
            }
            denom[tid] += (s0 + s1) + (s2 + s3);
        }
        __syncthreads();
    }

    // --- epilogue: relu(acc / denom) ---
#pragma unroll
    for (int m = 0; m < 8; m++) {
        int i = ty * 8 + m;
        float inv = 1.f / denom[i];
        float4 v0, v1;
        v0.x = fmaxf(acc[m][0] * inv, 0.f);
        v0.y = fmaxf(acc[m][1] * inv, 0.f);
        v0.z = fmaxf(acc[m][2] * inv, 0.f);
        v0.w = fmaxf(acc[m][3] * inv, 0.f);
        v1.x = fmaxf(acc[m][4] * inv, 0.f);
        v1.y = fmaxf(acc[m][5] * inv, 0.f);
        v1.z = fmaxf(acc[m][6] * inv, 0.f);
        v1.w = fmaxf(acc[m][7] * inv, 0.f);
        size_t base = ((size_t)(b * NNODE + i0 + i)) * DOUT + tx * 8;
        *(float4*)(out + base)     = v0;
        *(float4*)(out + base + 4) = v1;
    }
}

// ---------------------------------------------------------------------------
extern "C" void kernel_launch(void* const* d_in, const int* in_sizes, int n_in,
                              void* d_out, int out_size) {
    const float* x   = (const float*)d_in[0];   // [8,2048,256]
    const int*   adj = (const int*)  d_in[1];   // [8,2048,2048]
    const float* W   = (const float*)d_in[2];   // [128,256]
    const float* a   = (const float*)d_in[3];   // [256]
    float*       out = (float*)d_out;           // [8,2048,128]

    cudaFuncSetAttribute(attn_kernel, cudaFuncAttributeMaxDynamicSharedMemorySize,
                         SMEM_B_BYTES);

    wh_kernel<<<(BATCH * NNODE) / 128, 256>>>(x, W);
    sd_kernel<<<(BATCH * NNODE) / 8, 256>>>(a);
    attn_kernel<<<dim3(NNODE / 128, BATCH), 256, SMEM_B_BYTES>>>(adj, out);
}

// round 16
// speedup vs baseline: 2.4749x; 2.4749x over previous
#include <cuda_runtime.h>
#include <cuda_bf16.h>
#include <cstdint>

// Problem constants
#define BATCH 8
#define NNODE 2048
#define DIN   256
#define DOUT  128
#define ALPHA 0.2f

// Scratch (device globals: allocation-free)
__device__ __align__(16) float g_wh[BATCH * NNODE * DOUT];             // 8 MB
__device__ float g_s[BATCH * NNODE];
__device__ __align__(16) float g_d[BATCH * NNODE];
__device__ __align__(16) __nv_bfloat16 g_whT_hi[BATCH * DOUT * NNODE]; // 4 MB
__device__ __align__(16) __nv_bfloat16 g_whT_lo[BATCH * DOUT * NNODE]; // 4 MB

// ---------------------------------------------------------------------------
// Warp-MMA helpers (family-portable: ldmatrix + mma.sync, no 'a' features)
// ---------------------------------------------------------------------------
__device__ __forceinline__ uint32_t smem_u32(const void* p) {
    uint32_t a;
    asm("{ .reg .u64 t; cvta.to.shared.u64 t, %1; cvt.u32.u64 %0, t; }" : "=r"(a) : "l"(p));
    return a;
}

#define LDSM_X4(r, addr)                                                       \
    asm volatile("ldmatrix.sync.aligned.m8n8.x4.shared.b16 {%0,%1,%2,%3}, [%4];" \
                 : "=r"((r)[0]), "=r"((r)[1]), "=r"((r)[2]), "=r"((r)[3])      \
                 : "r"(addr))

#define MMA_BF16(c, a, b)                                                      \
    asm volatile("mma.sync.aligned.m16n8k16.row.col.f32.bf16.bf16.f32 "        \
                 "{%0,%1,%2,%3},{%4,%5,%6,%7},{%8,%9},{%0,%1,%2,%3};"          \
                 : "+f"((c)[0]), "+f"((c)[1]), "+f"((c)[2]), "+f"((c)[3])      \
                 : "r"((a)[0]), "r"((a)[1]), "r"((a)[2]), "r"((a)[3]),         \
                   "r"((b)[0]), "r"((b)[1]))

// ---------------------------------------------------------------------------
// Kernel A: wh[r][o] = sum_k x[r][k] * W[o][k]   (unchanged, 38us)
// ---------------------------------------------------------------------------
__global__ __launch_bounds__(256) void wh_kernel(const float* __restrict__ x,
                                                 const float* __restrict__ W) {
    __shared__ float xs[16][132];
    __shared__ float ws[16][132];

    const int tid = threadIdx.x;
    const int ty = tid >> 4;
    const int tx = tid & 15;
    const int row0 = blockIdx.x * 128;

    float acc[8][8];
#pragma unroll
    for (int m = 0; m < 8; m++)
#pragma unroll
        for (int n = 0; n < 8; n++) acc[m][n] = 0.f;

    for (int k0 = 0; k0 < DIN; k0 += 16) {
#pragma unroll
        for (int t = 0; t < 2; t++) {
            int lin4 = t * 256 + tid;
            int r = lin4 >> 2, c4 = lin4 & 3;
            float4 v = *(const float4*)(x + (size_t)(row0 + r) * DIN + k0 + c4 * 4);
            xs[c4 * 4 + 0][r] = v.x; xs[c4 * 4 + 1][r] = v.y;
            xs[c4 * 4 + 2][r] = v.z; xs[c4 * 4 + 3][r] = v.w;
        }
#pragma unroll
        for (int t = 0; t < 2; t++) {
            int lin4 = t * 256 + tid;
            int o = lin4 >> 2, c4 = lin4 & 3;
            float4 v = *(const float4*)(W + (size_t)o * DIN + k0 + c4 * 4);
            ws[c4 * 4 + 0][o] = v.x; ws[c4 * 4 + 1][o] = v.y;
            ws[c4 * 4 + 2][o] = v.z; ws[c4 * 4 + 3][o] = v.w;
        }
        __syncthreads();
#pragma unroll
        for (int k = 0; k < 16; k++) {
            float a[8], b[8];
            *(float4*)(a)     = *(const float4*)&xs[k][ty * 8];
            *(float4*)(a + 4) = *(const float4*)&xs[k][ty * 8 + 4];
            *(float4*)(b)     = *(const float4*)&ws[k][tx * 8];
            *(float4*)(b + 4) = *(const float4*)&ws[k][tx * 8 + 4];
#pragma unroll
            for (int m = 0; m < 8; m++)
#pragma unroll
                for (int n = 0; n < 8; n++) acc[m][n] += a[m] * b[n];
        }
        __syncthreads();
    }
#pragma unroll
    for (int m = 0; m < 8; m++) {
        int r = row0 + ty * 8 + m;
        *(float4*)(g_wh + (size_t)r * DOUT + tx * 8) =
            make_float4(acc[m][0], acc[m][1], acc[m][2], acc[m][3]);
        *(float4*)(g_wh + (size_t)r * DOUT + tx * 8 + 4) =
            make_float4(acc[m][4], acc[m][5], acc[m][6], acc[m][7]);
    }
}

// ---------------------------------------------------------------------------
// Kernel S: s/d projections (unchanged)
// ---------------------------------------------------------------------------
__global__ __launch_bounds__(256) void sd_kernel(const float* __restrict__ a) {
    int row  = blockIdx.x * 8 + (threadIdx.x >> 5);
    int lane = threadIdx.x & 31;
    const float* whr = g_wh + (size_t)row * DOUT;
    float s = 0.f, d = 0.f;
#pragma unroll
    for (int t = 0; t < 4; t++) {
        int o = lane + t * 32;
        float v = whr[o];
        s += v * a[o];
        d += v * a[DOUT + o];
    }
#pragma unroll
    for (int off = 16; off > 0; off >>= 1) {
        s += __shfl_xor_sync(0xFFFFFFFFu, s, off);
        d += __shfl_xor_sync(0xFFFFFFFFu, d, off);
    }
    if (lane == 0) { g_s[row] = s; g_d[row] = d; }
}

// ---------------------------------------------------------------------------
// Kernel T: whT split: g_whT_hi/lo[b][o][j] = split_bf16(wh[b*N+j][o])
// ---------------------------------------------------------------------------
__global__ __launch_bounds__(256) void wht_kernel() {
    __shared__ float t[32][33];
    int b = blockIdx.z, o0 = blockIdx.y * 32, j0 = blockIdx.x * 32;
    int tx = threadIdx.x, ty = threadIdx.y;   // 32 x 8
#pragma unroll
    for (int r = 0; r < 32; r += 8)
        t[ty + r][tx] = g_wh[(size_t)(b * NNODE + j0 + ty + r) * DOUT + o0 + tx];
    __syncthreads();
#pragma unroll
    for (int r = 0; r < 32; r += 8) {
        float v = t[tx][ty + r];
        __nv_bfloat16 hi = __float2bfloat16_rn(v);
        __nv_bfloat16 lo = __float2bfloat16_rn(v - __bfloat162float(hi));
        size_t idx = (size_t)(b * DOUT + o0 + ty + r) * NNODE + j0 + tx;
        g_whT_hi[idx] = hi;
        g_whT_lo[idx] = lo;
    }
}

// ---------------------------------------------------------------------------
// Kernel B: fused attention with warp-level bf16 mma.sync, split-3 GEMM.
//   SMEM tiles: A(hi/lo) = w tile [i=128][j=128] row-major, stride 136 elems.
//               B(hi/lo) = whT tile [o=128][j=128] row-major, stride 136.
//   Warp grid 2x4; each warp -> 64x32 output slab; m16n8k16 MMAs.
//   B fragments use NON-trans ldmatrix (tile is [n][k] row-major).
// ---------------------------------------------------------------------------
#define S_ELEM  136
#define S_BYTES 272
#define A_HI_O  0
#define A_LO_O  34816
#define B_HI_O  69632
#define B_LO_O  104448
#define DEN_O   139264
#define ATT_SMEM (DEN_O + 512 + 16)

__global__ __launch_bounds__(256) void attn_kernel(const int* __restrict__ adj,
                                                   float* __restrict__ out) {
    extern __shared__ __align__(16) char sm[];
    const uint32_t sb = smem_u32(sm);

    const int tid  = threadIdx.x;
    const int lane = tid & 31;
    const int warp = tid >> 5;
    const int wm   = warp >> 2;        // 0..1  (row slab of 64)
    const int wn   = warp & 3;         // 0..3  (col slab of 32)
    const int b    = blockIdx.y;
    const int i0   = blockIdx.x * 128;

    const int irow = tid >> 1;         // row this thread builds (0..127)
    const int jh   = (tid & 1) * 64;   // j half
    const float s_i = g_s[b * NNODE + i0 + irow];
    float den = 0.f;

    float acc[4][4][4];
#pragma unroll
    for (int mt = 0; mt < 4; mt++)
#pragma unroll
        for (int nt = 0; nt < 4; nt++)
#pragma unroll
            for (int e = 0; e < 4; e++) acc[mt][nt][e] = 0.f;

    // ldmatrix per-lane base offsets
    // A (m16xk16 via x4): lanes 0-15 -> rows 0-15 k0-7; lanes 16-31 -> rows 0-15 k8-15
    const uint32_t aoff = (uint32_t)(lane & 15) * S_BYTES + (uint32_t)(lane >> 4) * 16;
    const uint32_t aHiBase = sb + A_HI_O + aoff + (uint32_t)(wm * 64) * S_BYTES;
    const uint32_t aLoBase = sb + A_LO_O + aoff + (uint32_t)(wm * 64) * S_BYTES;
    // B (n16xk16 via x4, NON-trans from [n][k]): m0=n0-7/k0-7, m1=n0-7/k8-15,
    // m2=n8-15/k0-7, m3=n8-15/k8-15
    const uint32_t boff = (uint32_t)((lane & 7) + ((lane >> 4) << 3)) * S_BYTES +
                          (uint32_t)((lane >> 3) & 1) * 16;
    const uint32_t bHiBase = sb + B_HI_O + boff + (uint32_t)(wn * 32) * S_BYTES;
    const uint32_t bLoBase = sb + B_LO_O + boff + (uint32_t)(wn * 32) * S_BYTES;

    for (int jt = 0; jt < 16; jt++) {
        const int j0 = jt * 128;

        // ---- B tiles: whT hi/lo [o][j], padded row-major ----
        const __nv_bfloat16* bhp = g_whT_hi + (size_t)b * DOUT * NNODE + j0;
        const __nv_bfloat16* blp = g_whT_lo + (size_t)b * DOUT * NNODE + j0;
#pragma unroll
        for (int it = 0; it < 8; it++) {
            int lin = it * 256 + tid;
            int o = lin >> 4, jg = lin & 15;
            size_t g = (size_t)o * NNODE + jg * 8;
            uint32_t off = (uint32_t)o * S_BYTES + (uint32_t)jg * 16;
            *(uint4*)(sm + B_HI_O + off) = *(const uint4*)(bhp + g);
            *(uint4*)(sm + B_LO_O + off) = *(const uint4*)(blp + g);
        }

        // ---- A tile: w = adj ? exp(lrelu(s_i + d_j)) : 0, split hi/lo ----
        const int*   arow = adj + (size_t)(b * NNODE + i0 + irow) * NNODE + j0 + jh;
        const float* drow = g_d + b * NNODE + j0 + jh;
        float ds = 0.f;
#pragma unroll
        for (int gI = 0; gI < 8; gI++) {
            int4   q0 = ((const int4*)arow)[2 * gI];
            int4   q1 = ((const int4*)arow)[2 * gI + 1];
            float4 d0 = ((const float4*)drow)[2 * gI];
            float4 d1 = ((const float4*)drow)[2 * gI + 1];
            float w[8];
            float e;
            e = s_i + d0.x; e = fmaxf(e, ALPHA * e); w[0] = q0.x ? __expf(e) : 0.f;
            e = s_i + d0.y; e = fmaxf(e, ALPHA * e); w[1] = q0.y ? __expf(e) : 0.f;
            e = s_i + d0.z; e = fmaxf(e, ALPHA * e); w[2] = q0.z ? __expf(e) : 0.f;
            e = s_i + d0.w; e = fmaxf(e, ALPHA * e); w[3] = q0.w ? __expf(e) : 0.f;
            e = s_i + d1.x; e = fmaxf(e, ALPHA * e); w[4] = q1.x ? __expf(e) : 0.f;
            e = s_i + d1.y; e = fmaxf(e, ALPHA * e); w[5] = q1.y ? __expf(e) : 0.f;
            e = s_i + d1.z; e = fmaxf(e, ALPHA * e); w[6] = q1.z ? __expf(e) : 0.f;
            e = s_i + d1.w; e = fmaxf(e, ALPHA * e); w[7] = q1.w ? __expf(e) : 0.f;

            uint32_t hp[4], lp[4];
#pragma unroll
            for (int u = 0; u < 4; u++) {
                float w0 = w[2 * u], w1 = w[2 * u + 1];
                ds += w0 + w1;
                __nv_bfloat16 h0 = __float2bfloat16_rn(w0);
                __nv_bfloat16 h1 = __float2bfloat16_rn(w1);
                __nv_bfloat16 l0 = __float2bfloat16_rn(w0 - __bfloat162float(h0));
                __nv_bfloat16 l1 = __float2bfloat16_rn(w1 - __bfloat162float(h1));
                hp[u] = (uint32_t)__bfloat16_as_ushort(h0) |
                        ((uint32_t)__bfloat16_as_ushort(h1) << 16);
                lp[u] = (uint32_t)__bfloat16_as_ushort(l0) |
                        ((uint32_t)__bfloat16_as_ushort(l1) << 16);
            }
            uint32_t off = (uint32_t)irow * S_BYTES + (uint32_t)(jh + gI * 8) * 2;
            *(uint4*)(sm + A_HI_O + off) = make_uint4(hp[0], hp[1], hp[2], hp[3]);
            *(uint4*)(sm + A_LO_O + off) = make_uint4(lp[0], lp[1], lp[2], lp[3]);
        }
        float other = __shfl_xor_sync(0xFFFFFFFFu, ds, 1);
        if ((tid & 1) == 0) den += ds + other;

        __syncthreads();

        // ---- MMA: acc += Ahi*Bhi' + Ahi*Blo' + Alo*Bhi' over K=128 ----
#pragma unroll
        for (int ks = 0; ks < 8; ks++) {
            const uint32_t kb = (uint32_t)ks * 32;

            uint32_t Ah[4][4];
#pragma unroll
            for (int mt = 0; mt < 4; mt++)
                LDSM_X4(Ah[mt], aHiBase + (uint32_t)(mt * 16) * S_BYTES + kb);

            uint32_t Bh[4][2];
            {
                uint32_t t[4];
                LDSM_X4(t, bHiBase + kb);
                Bh[0][0] = t[0]; Bh[0][1] = t[1]; Bh[1][0] = t[2]; Bh[1][1] = t[3];
                LDSM_X4(t, bHiBase + 16u * S_BYTES + kb);
                Bh[2][0] = t[0]; Bh[2][1] = t[1]; Bh[3][0] = t[2]; Bh[3][1] = t[3];
            }
#pragma unroll
            for (int mt = 0; mt < 4; mt++)
#pragma unroll
                for (int nt = 0; nt < 4; nt++) MMA_BF16(acc[mt][nt], Ah[mt], Bh[nt]);

            uint32_t Bl[4][2];
            {
                uint32_t t[4];
                LDSM_X4(t, bLoBase + kb);
                Bl[0][0] = t[0]; Bl[0][1] = t[1]; Bl[1][0] = t[2]; Bl[1][1] = t[3];
                LDSM_X4(t, bLoBase + 16u * S_BYTES + kb);
                Bl[2][0] = t[0]; Bl[2][1] = t[1]; Bl[3][0] = t[2]; Bl[3][1] = t[3];
            }
#pragma unroll
            for (int mt = 0; mt < 4; mt++)
#pragma unroll
                for (int nt = 0; nt < 4; nt++) MMA_BF16(acc[mt][nt], Ah[mt], Bl[nt]);

            uint32_t Al[4][4];
#pragma unroll
            for (int mt = 0; mt < 4; mt++)
                LDSM_X4(Al[mt], aLoBase + (uint32_t)(mt * 16) * S_BYTES + kb);
#pragma unroll
            for (int mt = 0; mt < 4; mt++)
#pragma unroll
                for (int nt = 0; nt < 4; nt++) MMA_BF16(acc[mt][nt], Al[mt], Bh[nt]);
        }
        __syncthreads();
    }

    // ---- epilogue: relu(acc / denom) ----
    if ((tid & 1) == 0) *(float*)(sm + DEN_O + irow * 4) = den;
    __syncthreads();

#pragma unroll
    for (int mt = 0; mt < 4; mt++) {
        int r0 = wm * 64 + mt * 16 + (lane >> 2);
        float inv0 = 1.f / *(const float*)(sm + DEN_O + r0 * 4);
        float inv1 = 1.f / *(const float*)(sm + DEN_O + (r0 + 8) * 4);
        float* row0 = out + (size_t)(b * NNODE + i0 + r0) * DOUT;
        float* row1 = out + (size_t)(b * NNODE + i0 + r0 + 8) * DOUT;
#pragma unroll
        for (int nt = 0; nt < 4; nt++) {
            int col = wn * 32 + nt * 8 + (lane & 3) * 2;
            float2 v0, v1;
            v0.x = fmaxf(acc[mt][nt][0] * inv0, 0.f);
            v0.y = fmaxf(acc[mt][nt][1] * inv0, 0.f);
            v1.x = fmaxf(acc[mt][nt][2] * inv1, 0.f);
            v1.y = fmaxf(acc[mt][nt][3] * inv1, 0.f);
            *(float2*)(row0 + col) = v0;
            *(float2*)(row1 + col) = v1;
        }
    }
}

// ---------------------------------------------------------------------------
extern "C" void kernel_launch(void* const* d_in, const int* in_sizes, int n_in,
                              void* d_out, int out_size) {
    const float* x   = (const float*)d_in[0];   // [8,2048,256]
    const int*   adj = (const int*)  d_in[1];   // [8,2048,2048]
    const float* W   = (const float*)d_in[2];   // [128,256]
    const float* a   = (const float*)d_in[3];   // [256]
    float*       out = (float*)d_out;           // [8,2048,128]

    cudaFuncSetAttribute(attn_kernel, cudaFuncAttributeMaxDynamicSharedMemorySize,
                         ATT_SMEM);

    wh_kernel<<<(BATCH * NNODE) / 128, 256>>>(x, W);
    sd_kernel<<<(BATCH * NNODE) / 8, 256>>>(a);
    wht_kernel<<<dim3(NNODE / 32, DOUT / 32, BATCH), dim3(32, 8)>>>();
    attn_kernel<<<dim3(NNODE / 128, BATCH), 256, ATT_SMEM>>>(adj, out);
}

// round 17
// speedup vs baseline: 2.8160x; 1.1378x over previous
#include <cuda_runtime.h>
#include <cuda_bf16.h>
#include <cstdint>

// Problem constants
#define BATCH 8
#define NNODE 2048
#define DIN   256
#define DOUT  128
#define ALPHA 0.2f

// Scratch (device globals: allocation-free)
__device__ __align__(16) float g_wh[BATCH * NNODE * DOUT];             // 8 MB
__device__ float g_s[BATCH * NNODE];
__device__ __align__(16) float g_d[BATCH * NNODE];
__device__ __align__(16) __nv_bfloat16 g_whT_hi[BATCH * DOUT * NNODE]; // 4 MB
__device__ __align__(16) __nv_bfloat16 g_whT_lo[BATCH * DOUT * NNODE]; // 4 MB
__device__ uint32_t g_adjmask[BATCH * NNODE * (NNODE / 32)];           // 4 MB

// ---------------------------------------------------------------------------
// Warp-MMA helpers (family-portable: ldmatrix + mma.sync)
// ---------------------------------------------------------------------------
__device__ __forceinline__ uint32_t smem_u32(const void* p) {
    uint32_t a;
    asm("{ .reg .u64 t; cvta.to.shared.u64 t, %1; cvt.u32.u64 %0, t; }" : "=r"(a) : "l"(p));
    return a;
}

#define LDSM_X4(r, addr)                                                       \
    asm volatile("ldmatrix.sync.aligned.m8n8.x4.shared.b16 {%0,%1,%2,%3}, [%4];" \
                 : "=r"((r)[0]), "=r"((r)[1]), "=r"((r)[2]), "=r"((r)[3])      \
                 : "r"(addr))

#define MMA_BF16(c, a, b)                                                      \
    asm volatile("mma.sync.aligned.m16n8k16.row.col.f32.bf16.bf16.f32 "        \
                 "{%0,%1,%2,%3},{%4,%5,%6,%7},{%8,%9},{%0,%1,%2,%3};"          \
                 : "+f"((c)[0]), "+f"((c)[1]), "+f"((c)[2]), "+f"((c)[3])      \
                 : "r"((a)[0]), "r"((a)[1]), "r"((a)[2]), "r"((a)[3]),         \
                   "r"((b)[0]), "r"((b)[1]))

// ---------------------------------------------------------------------------
// Kernel A: wh[r][o] = sum_k x[r][k] * W[o][k]   (unchanged, 38us)
// ---------------------------------------------------------------------------
__global__ __launch_bounds__(256) void wh_kernel(const float* __restrict__ x,
                                                 const float* __restrict__ W) {
    __shared__ float xs[16][132];
    __shared__ float ws[16][132];

    const int tid = threadIdx.x;
    const int ty = tid >> 4;
    const int tx = tid & 15;
    const int row0 = blockIdx.x * 128;

    float acc[8][8];
#pragma unroll
    for (int m = 0; m < 8; m++)
#pragma unroll
        for (int n = 0; n < 8; n++) acc[m][n] = 0.f;

    for (int k0 = 0; k0 < DIN; k0 += 16) {
#pragma unroll
        for (int t = 0; t < 2; t++) {
            int lin4 = t * 256 + tid;
            int r = lin4 >> 2, c4 = lin4 & 3;
            float4 v = *(const float4*)(x + (size_t)(row0 + r) * DIN + k0 + c4 * 4);
            xs[c4 * 4 + 0][r] = v.x; xs[c4 * 4 + 1][r] = v.y;
            xs[c4 * 4 + 2][r] = v.z; xs[c4 * 4 + 3][r] = v.w;
        }
#pragma unroll
        for (int t = 0; t < 2; t++) {
            int lin4 = t * 256 + tid;
            int o = lin4 >> 2, c4 = lin4 & 3;
            float4 v = *(const float4*)(W + (size_t)o * DIN + k0 + c4 * 4);
            ws[c4 * 4 + 0][o] = v.x; ws[c4 * 4 + 1][o] = v.y;
            ws[c4 * 4 + 2][o] = v.z; ws[c4 * 4 + 3][o] = v.w;
        }
        __syncthreads();
#pragma unroll
        for (int k = 0; k < 16; k++) {
            float a[8], b[8];
            *(float4*)(a)     = *(const float4*)&xs[k][ty * 8];
            *(float4*)(a + 4) = *(const float4*)&xs[k][ty * 8 + 4];
            *(float4*)(b)     = *(const float4*)&ws[k][tx * 8];
            *(float4*)(b + 4) = *(const float4*)&ws[k][tx * 8 + 4];
#pragma unroll
            for (int m = 0; m < 8; m++)
#pragma unroll
                for (int n = 0; n < 8; n++) acc[m][n] += a[m] * b[n];
        }
        __syncthreads();
    }
#pragma unroll
    for (int m = 0; m < 8; m++) {
        int r = row0 + ty * 8 + m;
        *(float4*)(g_wh + (size_t)r * DOUT + tx * 8) =
            make_float4(acc[m][0], acc[m][1], acc[m][2], acc[m][3]);
        *(float4*)(g_wh + (size_t)r * DOUT + tx * 8 + 4) =
            make_float4(acc[m][4], acc[m][5], acc[m][6], acc[m][7]);
    }
}

// ---------------------------------------------------------------------------
// Kernel S: s/d projections (unchanged)
// ---------------------------------------------------------------------------
__global__ __launch_bounds__(256) void sd_kernel(const float* __restrict__ a) {
    int row  = blockIdx.x * 8 + (threadIdx.x >> 5);
    int lane = threadIdx.x & 31;
    const float* whr = g_wh + (size_t)row * DOUT;
    float s = 0.f, d = 0.f;
#pragma unroll
    for (int t = 0; t < 4; t++) {
        int o = lane + t * 32;
        float v = whr[o];
        s += v * a[o];
        d += v * a[DOUT + o];
    }
#pragma unroll
    for (int off = 16; off > 0; off >>= 1) {
        s += __shfl_xor_sync(0xFFFFFFFFu, s, off);
        d += __shfl_xor_sync(0xFFFFFFFFu, d, off);
    }
    if (lane == 0) { g_s[row] = s; g_d[row] = d; }
}

// ---------------------------------------------------------------------------
// Kernel T: whT split: g_whT_hi/lo[b][o][j] = split_bf16(wh[b*N+j][o])
// ---------------------------------------------------------------------------
__global__ __launch_bounds__(256) void wht_kernel() {
    __shared__ float t[32][33];
    int b = blockIdx.z, o0 = blockIdx.y * 32, j0 = blockIdx.x * 32;
    int tx = threadIdx.x, ty = threadIdx.y;   // 32 x 8
#pragma unroll
    for (int r = 0; r < 32; r += 8)
        t[ty + r][tx] = g_wh[(size_t)(b * NNODE + j0 + ty + r) * DOUT + o0 + tx];
    __syncthreads();
#pragma unroll
    for (int r = 0; r < 32; r += 8) {
        float v = t[tx][ty + r];
        __nv_bfloat16 hi = __float2bfloat16_rn(v);
        __nv_bfloat16 lo = __float2bfloat16_rn(v - __bfloat162float(hi));
        size_t idx = (size_t)(b * DOUT + o0 + ty + r) * NNODE + j0 + tx;
        g_whT_hi[idx] = hi;
        g_whT_lo[idx] = lo;
    }
}

// ---------------------------------------------------------------------------
// Kernel M: adj -> bitmask.  One warp packs 1024 consecutive ints into 32
// mask words via ballot (word w bit b <-> adj[w*32+b]).  Fully coalesced.
// ---------------------------------------------------------------------------
__global__ __launch_bounds__(256) void adjmask_kernel(const int* __restrict__ adj) {
    int wg   = blockIdx.x * 8 + (threadIdx.x >> 5);
    int lane = threadIdx.x & 31;
    size_t base = (size_t)wg * 1024;
    uint32_t m = 0;
#pragma unroll
    for (int it = 0; it < 32; it++) {
        uint32_t bal = __ballot_sync(0xFFFFFFFFu, adj[base + it * 32 + lane] != 0);
        if (it == lane) m = bal;
    }
    g_adjmask[(size_t)wg * 32 + lane] = m;
}

// ---------------------------------------------------------------------------
// Kernel B: fused attention. 512 threads, 16 warps (4x4 warp grid, 32x32
// slabs). adj via bitmask (1 LDG.32 per thread per tile). Split-bf16 3-GEMM.
// ---------------------------------------------------------------------------
#define S_BYTES 272
#define A_HI_O  0
#define A_LO_O  34816
#define B_HI_O  69632
#define B_LO_O  104448
#define DEN_O   139264
#define ATT_SMEM (DEN_O + 512 + 16)

__global__ __launch_bounds__(512) void attn_kernel(float* __restrict__ out) {
    extern __shared__ __align__(16) char sm[];
    const uint32_t sb = smem_u32(sm);

    const int tid  = threadIdx.x;
    const int lane = tid & 31;
    const int warp = tid >> 5;
    const int wm   = warp >> 2;        // 0..3  (row slab of 32)
    const int wn   = warp & 3;         // 0..3  (col slab of 32)
    const int b    = blockIdx.y;
    const int i0   = blockIdx.x * 128;

    const int irow = tid >> 2;         // row this thread builds (0..127)
    const int jq   = tid & 3;          // j quarter (32 j's)
    const float s_i = g_s[b * NNODE + i0 + irow];
    float den = 0.f;

    float acc[2][4][4];
#pragma unroll
    for (int mt = 0; mt < 2; mt++)
#pragma unroll
        for (int nt = 0; nt < 4; nt++)
#pragma unroll
            for (int e = 0; e < 4; e++) acc[mt][nt][e] = 0.f;

    // ldmatrix per-lane base offsets
    // A (m16xk16 via x4): lanes 0-15 -> rows, lanes 16-31 -> +16B k-offset
    const uint32_t aoff = (uint32_t)(lane & 15) * S_BYTES + (uint32_t)(lane >> 4) * 16;
    const uint32_t aHiBase = sb + A_HI_O + aoff + (uint32_t)(wm * 32) * S_BYTES;
    const uint32_t aLoBase = sb + A_LO_O + aoff + (uint32_t)(wm * 32) * S_BYTES;
    // B (n16xk16 via x4, non-trans from [n][k] tile)
    const uint32_t boff = (uint32_t)((lane & 7) + ((lane >> 4) << 3)) * S_BYTES +
                          (uint32_t)((lane >> 3) & 1) * 16;
    const uint32_t bHiBase = sb + B_HI_O + boff + (uint32_t)(wn * 32) * S_BYTES;
    const uint32_t bLoBase = sb + B_LO_O + boff + (uint32_t)(wn * 32) * S_BYTES;

    const uint32_t* mrow = g_adjmask + ((size_t)(b * NNODE + i0 + irow) << 6) + jq;

    for (int jt = 0; jt < 16; jt++) {
        const int j0 = jt * 128;

        // mask word for this thread's 32 j's (issued early; ~600cyc hidden by
        // the B-tile loads below)
        uint32_t mask = mrow[jt * 4];

        // ---- B tiles: whT hi/lo [o][j], padded row-major; 4 uint4 each ----
        const __nv_bfloat16* bhp = g_whT_hi + (size_t)b * DOUT * NNODE + j0;
        const __nv_bfloat16* blp = g_whT_lo + (size_t)b * DOUT * NNODE + j0;
#pragma unroll
        for (int it = 0; it < 4; it++) {
            int lin = it * 512 + tid;
            int o = lin >> 4, jg = lin & 15;
            size_t g = (size_t)o * NNODE + jg * 8;
            uint32_t off = (uint32_t)o * S_BYTES + (uint32_t)jg * 16;
            *(uint4*)(sm + B_HI_O + off) = *(const uint4*)(bhp + g);
            *(uint4*)(sm + B_LO_O + off) = *(const uint4*)(blp + g);
        }

        // ---- A tile: w = maskbit ? exp(lrelu(s_i + d_j)) : 0, split hi/lo ----
        const float* drow = g_d + b * NNODE + j0 + jq * 32;
        float ds = 0.f;
        const uint32_t abase = (uint32_t)irow * S_BYTES + (uint32_t)(jq * 32) * 2;
#pragma unroll
        for (int gI = 0; gI < 8; gI++) {     // 4 j's per iter
            float4 dv = ((const float4*)drow)[gI];
            float w[4];
            float e;
            e = s_i + dv.x; e = fmaxf(e, ALPHA * e); w[0] = (mask >> (gI*4+0)) & 1u ? __expf(e) : 0.f;
            e = s_i + dv.y; e = fmaxf(e, ALPHA * e); w[1] = (mask >> (gI*4+1)) & 1u ? __expf(e) : 0.f;
            e = s_i + dv.z; e = fmaxf(e, ALPHA * e); w[2] = (mask >> (gI*4+2)) & 1u ? __expf(e) : 0.f;
            e = s_i + dv.w; e = fmaxf(e, ALPHA * e); w[3] = (mask >> (gI*4+3)) & 1u ? __expf(e) : 0.f;

            uint32_t hp[2], lp[2];
#pragma unroll
            for (int u = 0; u < 2; u++) {
                float w0 = w[2*u], w1 = w[2*u+1];
                ds += w0 + w1;
                __nv_bfloat16 h0 = __float2bfloat16_rn(w0);
                __nv_bfloat16 h1 = __float2bfloat16_rn(w1);
                __nv_bfloat16 l0 = __float2bfloat16_rn(w0 - __bfloat162float(h0));
                __nv_bfloat16 l1 = __float2bfloat16_rn(w1 - __bfloat162float(h1));
                hp[u] = (uint32_t)__bfloat16_as_ushort(h0) |
                        ((uint32_t)__bfloat16_as_ushort(h1) << 16);
                lp[u] = (uint32_t)__bfloat16_as_ushort(l0) |
                        ((uint32_t)__bfloat16_as_ushort(l1) << 16);
            }
            uint32_t off = abase + (uint32_t)gI * 8;
            *(uint2*)(sm + A_HI_O + off) = make_uint2(hp[0], hp[1]);
            *(uint2*)(sm + A_LO_O + off) = make_uint2(lp[0], lp[1]);
        }
        den += ds;

        __syncthreads();

        // ---- MMA: acc += Ahi*Bhi' + Ahi*Blo' + Alo*Bhi' over K=128 ----
#pragma unroll
        for (int ks = 0; ks < 8; ks++) {
            const uint32_t kb = (uint32_t)ks * 32;

            uint32_t Ah[2][4];
#pragma unroll
            for (int mt = 0; mt < 2; mt++)
                LDSM_X4(Ah[mt], aHiBase + (uint32_t)(mt * 16) * S_BYTES + kb);

            uint32_t Bh[4][2];
            {
                uint32_t t[4];
                LDSM_X4(t, bHiBase + kb);
                Bh[0][0] = t[0]; Bh[0][1] = t[1]; Bh[1][0] = t[2]; Bh[1][1] = t[3];
                LDSM_X4(t, bHiBase + 16u * S_BYTES + kb);
                Bh[2][0] = t[0]; Bh[2][1] = t[1]; Bh[3][0] = t[2]; Bh[3][1] = t[3];
            }
#pragma unroll
            for (int mt = 0; mt < 2; mt++)
#pragma unroll
                for (int nt = 0; nt < 4; nt++) MMA_BF16(acc[mt][nt], Ah[mt], Bh[nt]);

            uint32_t Bl[4][2];
            {
                uint32_t t[4];
                LDSM_X4(t, bLoBase + kb);
                Bl[0][0] = t[0]; Bl[0][1] = t[1]; Bl[1][0] = t[2]; Bl[1][1] = t[3];
                LDSM_X4(t, bLoBase + 16u * S_BYTES + kb);
                Bl[2][0] = t[0]; Bl[2][1] = t[1]; Bl[3][0] = t[2]; Bl[3][1] = t[3];
            }
#pragma unroll
            for (int mt = 0; mt < 2; mt++)
#pragma unroll
                for (int nt = 0; nt < 4; nt++) MMA_BF16(acc[mt][nt], Ah[mt], Bl[nt]);

            uint32_t Al[2][4];
#pragma unroll
            for (int mt = 0; mt < 2; mt++)
                LDSM_X4(Al[mt], aLoBase + (uint32_t)(mt * 16) * S_BYTES + kb);
#pragma unroll
            for (int mt = 0; mt < 2; mt++)
#pragma unroll
                for (int nt = 0; nt < 4; nt++) MMA_BF16(acc[mt][nt], Al[mt], Bh[nt]);
        }
        __syncthreads();
    }

    // ---- denominator: reduce across the 4 threads sharing a row ----
    den += __shfl_xor_sync(0xFFFFFFFFu, den, 1);
    den += __shfl_xor_sync(0xFFFFFFFFu, den, 2);
    if (jq == 0) *(float*)(sm + DEN_O + irow * 4) = den;
    __syncthreads();

    // ---- epilogue: relu(acc / denom) ----
#pragma unroll
    for (int mt = 0; mt < 2; mt++) {
        int r0 = wm * 32 + mt * 16 + (lane >> 2);
        float inv0 = 1.f / *(const float*)(sm + DEN_O + r0 * 4);
        float inv1 = 1.f / *(const float*)(sm + DEN_O + (r0 + 8) * 4);
        float* row0 = out + (size_t)(b * NNODE + i0 + r0) * DOUT;
        float* row1 = out + (size_t)(b * NNODE + i0 + r0 + 8) * DOUT;
#pragma unroll
        for (int nt = 0; nt < 4; nt++) {
            int col = wn * 32 + nt * 8 + (lane & 3) * 2;
            float2 v0, v1;
            v0.x = fmaxf(acc[mt][nt][0] * inv0, 0.f);
            v0.y = fmaxf(acc[mt][nt][1] * inv0, 0.f);
            v1.x = fmaxf(acc[mt][nt][2] * inv1, 0.f);
            v1.y = fmaxf(acc[mt][nt][3] * inv1, 0.f);
            *(float2*)(row0 + col) = v0;
            *(float2*)(row1 + col) = v1;
        }
    }
}

// ---------------------------------------------------------------------------
extern "C" void kernel_launch(void* const* d_in, const int* in_sizes, int n_in,
                              void* d_out, int out_size) {
    const float* x   = (const float*)d_in[0];   // [8,2048,256]
    const int*   adj = (const int*)  d_in[1];   // [8,2048,2048]
    const float* W   = (const float*)d_in[2];   // [128,256]
    const float* a   = (const float*)d_in[3];   // [256]
    float*       out = (float*)d_out;           // [8,2048,128]

    cudaFuncSetAttribute(attn_kernel, cudaFuncAttributeMaxDynamicSharedMemorySize,
                         ATT_SMEM);

    wh_kernel<<<(BATCH * NNODE) / 128, 256>>>(x, W);
    adjmask_kernel<<<(BATCH * NNODE * NNODE) / (1024 * 8), 256>>>(adj);
    sd_kernel<<<(BATCH * NNODE) / 8, 256>>>(a);
    wht_kernel<<<dim3(NNODE / 32, DOUT / 32, BATCH), dim3(32, 8)>>>();
    attn_kernel<<<dim3(NNODE / 128, BATCH), 512, ATT_SMEM>>>(out);
}